// round 1
// baseline (speedup 1.0000x reference)
#include <cuda_runtime.h>
#include <math.h>

#define T 32
#define N 512
#define E 64
#define F 64
#define HD 64
#define SLOPE 0.2f

// ---------------- device scratch (no allocations allowed) ----------------
__device__ float g_h[T * N * HD];       // 4 MB
__device__ float g_shyp[T * N];
__device__ float g_sind[T * N];
__device__ float g_emax[T * E];
__device__ float g_einv[T * E];
__device__ float g_ind[T * N * HD];     // 4 MB
__device__ int   g_adj_cnt[N];
__device__ int   g_adj_nbr[N * N];      // 1 MB
__device__ int   g_ne_cnt[N];
__device__ int   g_ne_lst[N * E];
__device__ int   g_en_cnt[E];
__device__ int   g_en_lst[E * N];

// ---------------- CSR builders (deterministic ballot compaction) ----------------
__global__ void k_csr_adj(const int* __restrict__ adj) {
    int w = (blockIdx.x * blockDim.x + threadIdx.x) >> 5;   // row i
    int lane = threadIdx.x & 31;
    if (w >= N) return;
    int cnt = 0;
    #pragma unroll
    for (int c = 0; c < N / 32; c++) {
        int j = c * 32 + lane;
        bool m = adj[w * N + j] != 0;
        unsigned b = __ballot_sync(0xffffffffu, m);
        if (m) g_adj_nbr[w * N + cnt + __popc(b & ((1u << lane) - 1u))] = j;
        cnt += __popc(b);
    }
    if (lane == 0) g_adj_cnt[w] = cnt;
}

__global__ void k_csr_ne(const int* __restrict__ Hm) {     // node -> member edges
    int w = (blockIdx.x * blockDim.x + threadIdx.x) >> 5;   // node n
    int lane = threadIdx.x & 31;
    if (w >= N) return;
    int cnt = 0;
    #pragma unroll
    for (int c = 0; c < E / 32; c++) {
        int e = c * 32 + lane;
        bool m = Hm[w * E + e] != 0;
        unsigned b = __ballot_sync(0xffffffffu, m);
        if (m) g_ne_lst[w * E + cnt + __popc(b & ((1u << lane) - 1u))] = e;
        cnt += __popc(b);
    }
    if (lane == 0) g_ne_cnt[w] = cnt;
}

__global__ void k_csr_en(const int* __restrict__ Hm) {     // edge -> member nodes
    int w = (blockIdx.x * blockDim.x + threadIdx.x) >> 5;   // edge e
    int lane = threadIdx.x & 31;
    if (w >= E) return;
    int cnt = 0;
    #pragma unroll
    for (int c = 0; c < N / 32; c++) {
        int n = c * 32 + lane;
        bool m = Hm[n * E + w] != 0;
        unsigned b = __ballot_sync(0xffffffffu, m);
        if (m) g_en_lst[w * N + cnt + __popc(b & ((1u << lane) - 1u))] = n;
        cnt += __popc(b);
    }
    if (lane == 0) g_en_cnt[w] = cnt;
}

// ---------------- h = x@W, s_hyp, s_ind ----------------
__global__ void k_h(const float* __restrict__ x, const float* __restrict__ W,
                    const float* __restrict__ ah, const float* __restrict__ ai) {
    int tid = threadIdx.x;
    int d = tid & 63;
    int r = blockIdx.x * 4 + (tid >> 6);      // row in [0, T*N)
    const float* xr = x + r * F;
    float acc = 0.f;
    #pragma unroll
    for (int k = 0; k < F; k++) acc = fmaf(xr[k], W[k * HD + d], acc);
    g_h[r * HD + d] = acc;

    __shared__ float sm[8];
    int warp = tid >> 5;
    // s_hyp
    float p = acc * ah[d];
    #pragma unroll
    for (int o = 16; o > 0; o >>= 1) p += __shfl_down_sync(0xffffffffu, p, o);
    if ((tid & 31) == 0) sm[warp] = p;
    __syncthreads();
    if (d == 0) {
        int g = tid >> 6;
        float s = sm[2 * g] + sm[2 * g + 1];
        g_shyp[r] = s >= 0.f ? s : SLOPE * s;
    }
    __syncthreads();
    // s_ind
    p = acc * ai[d];
    #pragma unroll
    for (int o = 16; o > 0; o >>= 1) p += __shfl_down_sync(0xffffffffu, p, o);
    if ((tid & 31) == 0) sm[warp] = p;
    __syncthreads();
    if (d == 0) {
        int g = tid >> 6;
        float s = sm[2 * g] + sm[2 * g + 1];
        g_sind[r] = s >= 0.f ? s : SLOPE * s;
    }
}

// ---------------- per (t, e) hyperedge softmax stats over member nodes ----------------
__global__ void k_estats() {
    int w = (blockIdx.x * blockDim.x + threadIdx.x) >> 5;   // (t, e)
    int lane = threadIdx.x & 31;
    if (w >= T * E) return;
    int t = w / E, e = w % E;
    int cnt = g_en_cnt[e];
    const int* lst = g_en_lst + e * N;
    const float* sh = g_shyp + t * N;
    float m = -3.0e38f;
    for (int i = lane; i < cnt; i += 32) m = fmaxf(m, sh[lst[i]]);
    #pragma unroll
    for (int o = 16; o > 0; o >>= 1) m = fmaxf(m, __shfl_xor_sync(0xffffffffu, m, o));
    float s = 0.f;
    for (int i = lane; i < cnt; i += 32) s += expf(sh[lst[i]] - m);
    #pragma unroll
    for (int o = 16; o > 0; o >>= 1) s += __shfl_xor_sync(0xffffffffu, s, o);
    if (lane == 0) { g_emax[w] = m; g_einv[w] = 1.f / s; }
}

// ---------------- industry = masked-softmax(adj) @ h ----------------
__global__ void k_industry() {
    int row = blockIdx.x;        // t*N + i
    int t = row >> 9;
    int i = row & (N - 1);
    int tid = threadIdx.x;       // 64 threads
    int deg = g_adj_cnt[i];
    const int* nbr = g_adj_nbr + i * N;
    const float* si = g_sind + t * N;
    __shared__ float smw[N];
    __shared__ float smr[2];

    float m = -3.0e38f;
    for (int k = tid; k < deg; k += 64) m = fmaxf(m, si[nbr[k]]);
    #pragma unroll
    for (int o = 16; o > 0; o >>= 1) m = fmaxf(m, __shfl_xor_sync(0xffffffffu, m, o));
    if ((tid & 31) == 0) smr[tid >> 5] = m;
    __syncthreads();
    m = fmaxf(smr[0], smr[1]);

    float s = 0.f;
    for (int k = tid; k < deg; k += 64) {
        float w = expf(si[nbr[k]] - m);
        smw[k] = w;
        s += w;
    }
    #pragma unroll
    for (int o = 16; o > 0; o >>= 1) s += __shfl_xor_sync(0xffffffffu, s, o);
    __syncthreads();
    if ((tid & 31) == 0) smr[tid >> 5] = s;
    __syncthreads();
    float inv = 1.f / (smr[0] + smr[1]);

    float acc = 0.f;
    for (int k = 0; k < deg; k++) {
        int j = nbr[k];
        acc = fmaf(smw[k] * inv, g_h[(t * N + j) * HD + tid], acc);
    }
    g_ind[row * HD + tid] = acc;
}

// ---------------- main: y8 (online softmax over member edges) + pair combine ----------------
__device__ __forceinline__ float edge_score(float f, int ny, int d, int lane, int warp,
                                            float* smf, float* smw,
                                            const float* Wc1s, const float* bc1s,
                                            const float* wc2s, float bc2) {
    __syncthreads();                 // protect previous smf/smw readers
    smf[ny * 65 + d] = f;
    __syncthreads();
    float p = bc1s[d];
    const float* fr = smf + ny * 65;
    #pragma unroll
    for (int k = 0; k < HD; k++) p = fmaf(fr[k], Wc1s[k * HD + d], p);
    p = fmaxf(p, 0.f) * wc2s[d];
    #pragma unroll
    for (int o = 16; o > 0; o >>= 1) p += __shfl_down_sync(0xffffffffu, p, o);
    if (lane == 0) smw[warp] = p;
    __syncthreads();
    return smw[ny * 2] + smw[ny * 2 + 1] + bc2;
}

__global__ void __launch_bounds__(256) k_main(float* __restrict__ out,
                       const float* __restrict__ Wc1g, const float* __restrict__ bc1g,
                       const float* __restrict__ wc2g, const float* __restrict__ bc2g) {
    __shared__ float Wc1s[HD * HD];
    __shared__ float bc1s[HD];
    __shared__ float wc2s[HD];
    __shared__ float smf[4 * 65];
    __shared__ float smw[8];
    __shared__ int sdeg[4];

    int tid = threadIdx.x;
    int ny = tid >> 6;
    int d = tid & 63;
    int lane = tid & 31;
    int warp = tid >> 5;
    int row = blockIdx.x * 4 + ny;          // t*N + n
    int t = row >> 9;
    int n = row & (N - 1);

    for (int k = tid; k < HD * HD; k += 256) Wc1s[k] = Wc1g[k];
    if (tid < HD) { bc1s[tid] = bc1g[tid]; wc2s[tid] = wc2g[tid]; }
    float bc2 = bc2g[0];
    int deg = g_ne_cnt[n];
    if (d == 0) sdeg[ny] = deg;
    __syncthreads();
    int maxdeg = max(max(sdeg[0], sdeg[1]), max(sdeg[2], sdeg[3]));

    float hv = g_h[row * HD + d];
    float shn = g_shyp[row];

    float M = -3.0e38f, S = 0.f, acc = 0.f;
    for (int it = 0; it < maxdeg; ++it) {
        bool active = it < deg;
        float a = 0.f;
        if (active) {
            int e = g_ne_lst[n * E + it];
            a = expf(shn - g_emax[t * E + e]) * g_einv[t * E + e];
        }
        float v = a * hv;
        float f = v > 0.f ? v : expm1f(v);        // elu; inactive -> f = 0
        float z = edge_score(f, ny, d, lane, warp, smf, smw, Wc1s, bc1s, wc2s, bc2);
        if (active) {
            float nM = fmaxf(M, z);
            float sc = expf(M - nM);
            float w = expf(z - nM);
            acc = acc * sc + w * f;
            S = S * sc + w;
            M = nM;
        }
    }
    float y8 = acc / S;                            // deg >= 1 guaranteed
    float indv = g_ind[row * HD + d];

    float z1 = edge_score(indv, ny, d, lane, warp, smf, smw, Wc1s, bc1s, wc2s, bc2);
    float z2 = edge_score(y8,   ny, d, lane, warp, smf, smw, Wc1s, bc1s, wc2s, bc2);

    float m2 = fmaxf(z1, z2);
    float w1 = expf(z1 - m2), w2 = expf(z2 - m2);
    out[row * HD + d] = (w1 * indv + w2 * y8) / (w1 + w2);
}

// ---------------- launch ----------------
extern "C" void kernel_launch(void* const* d_in, const int* in_sizes, int n_in,
                              void* d_out, int out_size) {
    // metadata order: x, H, adj, [nhid], W, a_hyp, a_ind, Wc1, bc1, wc2, bc2
    int off = (n_in >= 11) ? 1 : 0;     // skip nhid scalar if present
    const float* x   = (const float*)d_in[0];
    const int*   Hm  = (const int*)d_in[1];
    const int*   adj = (const int*)d_in[2];
    const float* W   = (const float*)d_in[3 + off];
    const float* ah  = (const float*)d_in[4 + off];
    const float* ai  = (const float*)d_in[5 + off];
    const float* Wc1 = (const float*)d_in[6 + off];
    const float* bc1 = (const float*)d_in[7 + off];
    const float* wc2 = (const float*)d_in[8 + off];
    const float* bc2 = (const float*)d_in[9 + off];
    float* out = (float*)d_out;

    k_csr_adj<<<N / 8, 256>>>(adj);
    k_csr_ne<<<N / 8, 256>>>(Hm);
    k_csr_en<<<E / 8, 256>>>(Hm);
    k_h<<<T * N / 4, 256>>>(x, W, ah, ai);
    k_estats<<<T * E / 8, 256>>>();
    k_industry<<<T * N, 64>>>();
    k_main<<<T * N / 4, 256>>>(out, Wc1, bc1, wc2, bc2);
}

// round 2
// speedup vs baseline: 1.3140x; 1.3140x over previous
#include <cuda_runtime.h>
#include <math.h>

#define T 32
#define N 512
#define E 64
#define F 64
#define HD 64
#define SLOPE 0.2f

// ---------------- device scratch (no allocations allowed) ----------------
__device__ float g_h[T * N * HD];       // 4 MB
__device__ float g_shyp[T * N];
__device__ float g_sind[T * N];
__device__ float g_emax[T * E];
__device__ float g_einv[T * E];
__device__ float g_ind[T * N * HD];     // 4 MB
__device__ int   g_adj_cnt[N];
__device__ int   g_adj_nbr[N * N];      // 1 MB
__device__ int   g_ne_cnt[N];
__device__ int   g_ne_lst[N * E];
__device__ int   g_en_cnt[E];
__device__ int   g_en_lst[E * N];

// ---------------- fused CSR builders (deterministic ballot compaction) ----------------
// grid: 64 blocks (adj rows) + 64 blocks (node->edge) + 8 blocks (edge->node), 256 thr
__global__ void k_csr(const int* __restrict__ adj, const int* __restrict__ Hm) {
    int b = blockIdx.x;
    int lane = threadIdx.x & 31;
    int wl = threadIdx.x >> 5;               // warp in block (0..7)
    if (b < 64) {                             // adjacency rows
        int i = b * 8 + wl;
        int cnt = 0;
        #pragma unroll
        for (int c = 0; c < N / 32; c++) {
            int j = c * 32 + lane;
            bool m = adj[i * N + j] != 0;
            unsigned bl = __ballot_sync(0xffffffffu, m);
            if (m) g_adj_nbr[i * N + cnt + __popc(bl & ((1u << lane) - 1u))] = j;
            cnt += __popc(bl);
        }
        if (lane == 0) g_adj_cnt[i] = cnt;
    } else if (b < 128) {                     // node -> member edges
        int n = (b - 64) * 8 + wl;
        int cnt = 0;
        #pragma unroll
        for (int c = 0; c < E / 32; c++) {
            int e = c * 32 + lane;
            bool m = Hm[n * E + e] != 0;
            unsigned bl = __ballot_sync(0xffffffffu, m);
            if (m) g_ne_lst[n * E + cnt + __popc(bl & ((1u << lane) - 1u))] = e;
            cnt += __popc(bl);
        }
        if (lane == 0) g_ne_cnt[n] = cnt;
    } else {                                  // edge -> member nodes
        int e = (b - 128) * 8 + wl;
        int cnt = 0;
        #pragma unroll
        for (int c = 0; c < N / 32; c++) {
            int n = c * 32 + lane;
            bool m = Hm[n * E + e] != 0;
            unsigned bl = __ballot_sync(0xffffffffu, m);
            if (m) g_en_lst[e * N + cnt + __popc(bl & ((1u << lane) - 1u))] = n;
            cnt += __popc(bl);
        }
        if (lane == 0) g_en_cnt[e] = cnt;
    }
}

// ---------------- h = x@W (smem-tiled GEMM) + fused s_hyp / s_ind ----------------
// 64 blocks x 32 rows. 256 threads, 2x4 register tile.
__global__ void __launch_bounds__(256) k_h(const float* __restrict__ x,
                                           const float* __restrict__ W,
                                           const float* __restrict__ ah,
                                           const float* __restrict__ ai) {
    __shared__ float xs[32][65];
    __shared__ float ws[64][65];
    int tid = threadIdx.x;
    int r0 = blockIdx.x * 32;

    for (int i = tid; i < 32 * 64; i += 256) {
        int r = i >> 6, c = i & 63;
        xs[r][c] = x[(r0 + r) * F + c];
    }
    for (int i = tid; i < 64 * 64; i += 256) {
        int r = i >> 6, c = i & 63;
        ws[r][c] = W[i];
    }
    __syncthreads();

    int ty = tid >> 4, tx = tid & 15;         // 16x16 thread grid
    float acc[2][4] = {{0.f,0.f,0.f,0.f},{0.f,0.f,0.f,0.f}};
    #pragma unroll 8
    for (int k = 0; k < 64; k++) {
        float xr0 = xs[ty * 2 + 0][k];
        float xr1 = xs[ty * 2 + 1][k];
        float wv[4];
        #pragma unroll
        for (int j = 0; j < 4; j++) wv[j] = ws[k][tx * 4 + j];
        #pragma unroll
        for (int j = 0; j < 4; j++) {
            acc[0][j] = fmaf(xr0, wv[j], acc[0][j]);
            acc[1][j] = fmaf(xr1, wv[j], acc[1][j]);
        }
    }
    __syncthreads();                           // xs reads done, reuse for h tile
    #pragma unroll
    for (int i = 0; i < 2; i++) {
        int r = ty * 2 + i;
        #pragma unroll
        for (int j = 0; j < 4; j++) xs[r][tx * 4 + j] = acc[i][j];
        float4 v = make_float4(acc[i][0], acc[i][1], acc[i][2], acc[i][3]);
        *(float4*)&g_h[(r0 + r) * HD + tx * 4] = v;
    }
    __syncthreads();

    // s_hyp / s_ind: 8 threads per row
    int row = tid >> 3, oct = tid & 7;
    float sh = 0.f, si = 0.f;
    #pragma unroll
    for (int k = 0; k < 8; k++) {
        float v = xs[row][oct * 8 + k];
        sh = fmaf(v, __ldg(&ah[oct * 8 + k]), sh);
        si = fmaf(v, __ldg(&ai[oct * 8 + k]), si);
    }
    #pragma unroll
    for (int o = 4; o > 0; o >>= 1) {
        sh += __shfl_xor_sync(0xffffffffu, sh, o);
        si += __shfl_xor_sync(0xffffffffu, si, o);
    }
    if (oct == 0) {
        g_shyp[r0 + row] = sh >= 0.f ? sh : SLOPE * sh;
        g_sind[r0 + row] = si >= 0.f ? si : SLOPE * si;
    }
}

// ---------------- fused: industry attention (blocks 0..4095) + hyperedge stats (4096..4351) ----------------
__global__ void __launch_bounds__(256) k_mid() {
    int b = blockIdx.x;
    int tid = threadIdx.x;
    int lane = tid & 31;
    if (b < 4096) {
        // industry: 4 rows per block, 64 threads each
        __shared__ float smw4[4][512];
        __shared__ float smrA[8];
        __shared__ float smrB[8];
        int g = tid >> 6;
        int d = tid & 63;
        int warp = tid >> 5;
        int row = b * 4 + g;                   // t*N + i
        int t = row >> 9;
        int i = row & (N - 1);
        int deg = g_adj_cnt[i];
        const int* nbr = g_adj_nbr + i * N;
        const float* si = g_sind + t * N;

        float m = -3.0e38f;
        for (int k = d; k < deg; k += 64) m = fmaxf(m, si[nbr[k]]);
        #pragma unroll
        for (int o = 16; o > 0; o >>= 1) m = fmaxf(m, __shfl_xor_sync(0xffffffffu, m, o));
        if (lane == 0) smrA[warp] = m;
        __syncthreads();
        m = fmaxf(smrA[g * 2], smrA[g * 2 + 1]);

        float s = 0.f;
        for (int k = d; k < deg; k += 64) {
            float w = expf(si[nbr[k]] - m);
            smw4[g][k] = w;
            s += w;
        }
        #pragma unroll
        for (int o = 16; o > 0; o >>= 1) s += __shfl_xor_sync(0xffffffffu, s, o);
        if (lane == 0) smrB[warp] = s;
        __syncthreads();
        float inv = 1.f / (smrB[g * 2] + smrB[g * 2 + 1]);

        const float* hb = g_h + t * N * HD;
        float a0 = 0.f, a1 = 0.f, a2 = 0.f, a3 = 0.f;
        int k = 0;
        for (; k + 4 <= deg; k += 4) {
            int j0 = nbr[k], j1 = nbr[k + 1], j2 = nbr[k + 2], j3 = nbr[k + 3];
            a0 = fmaf(smw4[g][k],     hb[j0 * HD + d], a0);
            a1 = fmaf(smw4[g][k + 1], hb[j1 * HD + d], a1);
            a2 = fmaf(smw4[g][k + 2], hb[j2 * HD + d], a2);
            a3 = fmaf(smw4[g][k + 3], hb[j3 * HD + d], a3);
        }
        for (; k < deg; k++) a0 = fmaf(smw4[g][k], hb[nbr[k] * HD + d], a0);
        g_ind[row * HD + d] = ((a0 + a1) + (a2 + a3)) * inv;
    } else {
        // hyperedge softmax stats: one (t,e) per warp
        int w = (b - 4096) * 8 + (tid >> 5);   // 0..2047
        int t = w / E, e = w % E;
        int cnt = g_en_cnt[e];
        const int* lst = g_en_lst + e * N;
        const float* sh = g_shyp + t * N;
        float m = -3.0e38f;
        for (int i = lane; i < cnt; i += 32) m = fmaxf(m, sh[lst[i]]);
        #pragma unroll
        for (int o = 16; o > 0; o >>= 1) m = fmaxf(m, __shfl_xor_sync(0xffffffffu, m, o));
        float s = 0.f;
        for (int i = lane; i < cnt; i += 32) s += expf(sh[lst[i]] - m);
        #pragma unroll
        for (int o = 16; o > 0; o >>= 1) s += __shfl_xor_sync(0xffffffffu, s, o);
        if (lane == 0) { g_emax[w] = m; g_einv[w] = 1.f / s; }
    }
}

// ---------------- main: y8 (online softmax over member edges) + pair combine ----------------
// 4 nodes per block, 256 threads. Wc1 column register-resident per thread.
#define EDGE_SCORE(fval, zout)                                                   \
    {                                                                            \
        smf[ny][d] = (fval);                                                     \
        __syncthreads();                                                         \
        float p0 = 0.f, p1 = 0.f, p2 = 0.f, p3 = 0.f;                            \
        const float* fp = smf[ny];                                               \
        _Pragma("unroll")                                                        \
        for (int k = 0; k < 64; k += 4) {                                        \
            p0 = fmaf(fp[k],     Wreg[k],     p0);                               \
            p1 = fmaf(fp[k + 1], Wreg[k + 1], p1);                               \
            p2 = fmaf(fp[k + 2], Wreg[k + 2], p2);                               \
            p3 = fmaf(fp[k + 3], Wreg[k + 3], p3);                               \
        }                                                                        \
        float p = ((p0 + p1) + (p2 + p3)) + bc1d;                                \
        p = fmaxf(p, 0.f) * wc2d;                                                \
        _Pragma("unroll")                                                        \
        for (int o = 16; o > 0; o >>= 1) p += __shfl_down_sync(0xffffffffu, p, o);\
        if (lane == 0) smw[warp] = p;                                            \
        __syncthreads();                                                         \
        (zout) = smw[ny * 2] + smw[ny * 2 + 1] + bc2;                            \
    }

__global__ void __launch_bounds__(256) k_main(float* __restrict__ out,
                       const float* __restrict__ Wc1g, const float* __restrict__ bc1g,
                       const float* __restrict__ wc2g, const float* __restrict__ bc2g) {
    __shared__ float Wst[HD * HD];
    __shared__ float smf[4][HD];
    __shared__ float smw[8];
    __shared__ int sdeg[4];

    int tid = threadIdx.x;
    int ny = tid >> 6;
    int d = tid & 63;
    int lane = tid & 31;
    int warp = tid >> 5;
    int row = blockIdx.x * 4 + ny;          // t*N + n
    int t = row >> 9;
    int n = row & (N - 1);

    for (int k = tid; k < HD * HD; k += 256) Wst[k] = Wc1g[k];
    int deg = g_ne_cnt[n];
    if (d == 0) sdeg[ny] = deg;
    __syncthreads();
    float Wreg[64];
    #pragma unroll
    for (int k = 0; k < 64; k++) Wreg[k] = Wst[k * 64 + d];   // conflict-free
    int maxdeg = max(max(sdeg[0], sdeg[1]), max(sdeg[2], sdeg[3]));

    float bc1d = bc1g[d], wc2d = wc2g[d], bc2 = bc2g[0];
    float hv = g_h[row * HD + d];
    float shn = g_shyp[row];
    const int* nel = g_ne_lst + n * E;
    const float* em = g_emax + t * E;
    const float* ei = g_einv + t * E;

    float M = -3.0e38f, S = 0.f, acc = 0.f;
    for (int it = 0; it < maxdeg; ++it) {
        bool active = it < deg;
        float f = 0.f;
        if (active) {
            int e = nel[it];
            float a = expf(shn - em[e]) * ei[e];
            float v = a * hv;
            f = v > 0.f ? v : expm1f(v);       // elu
        }
        float z;
        EDGE_SCORE(f, z);
        if (active) {
            float nM = fmaxf(M, z);
            float sc = expf(M - nM);
            float w = expf(z - nM);
            acc = fmaf(w, f, acc * sc);
            S = fmaf(w, 1.f, S * sc);
            M = nM;
        }
    }
    float y8 = acc / S;                        // deg >= 1 guaranteed
    float indv = g_ind[row * HD + d];

    float z1, z2;
    EDGE_SCORE(indv, z1);
    EDGE_SCORE(y8, z2);

    float m2 = fmaxf(z1, z2);
    float w1 = expf(z1 - m2), w2 = expf(z2 - m2);
    out[row * HD + d] = (w1 * indv + w2 * y8) / (w1 + w2);
}

// ---------------- launch ----------------
extern "C" void kernel_launch(void* const* d_in, const int* in_sizes, int n_in,
                              void* d_out, int out_size) {
    int off = (n_in >= 11) ? 1 : 0;     // skip nhid scalar if present
    const float* x   = (const float*)d_in[0];
    const int*   Hm  = (const int*)d_in[1];
    const int*   adj = (const int*)d_in[2];
    const float* W   = (const float*)d_in[3 + off];
    const float* ah  = (const float*)d_in[4 + off];
    const float* ai  = (const float*)d_in[5 + off];
    const float* Wc1 = (const float*)d_in[6 + off];
    const float* bc1 = (const float*)d_in[7 + off];
    const float* wc2 = (const float*)d_in[8 + off];
    const float* bc2 = (const float*)d_in[9 + off];
    float* out = (float*)d_out;

    k_csr<<<136, 256>>>(adj, Hm);
    k_h<<<T * N / 32, 256>>>(x, W, ah, ai);
    k_mid<<<4096 + 256, 256>>>();
    k_main<<<T * N / 4, 256>>>(out, Wc1, bc1, wc2, bc2);
}